// round 15
// baseline (speedup 1.0000x reference)
#include <cuda_runtime.h>
#include <cuda_fp16.h>
#include <math.h>
#include <stdint.h>

// VectorQuantizer: fp16 (HFMA2) screen + bit-exact fp32 rescreen of near-ties.
//
// Reference semantics (R6/R8-proven bit-exact):
//   v_k = fl( fl(sumxx + cnorm_k) - 2*dot_k ), dot/sumxx/cnorm accumulated
//   sequentially over d=0..63 in fp32; argmin, first-min tie-break.
//
// Screen (per vector): s_k = cnorm_k - 2*dot16_k with dot16 from packed-fp16
// HFMA2 (2 dims per instr). Rows whose top-2 screen gap < MARGIN get an exact
// full rescan (R10-validated machinery). Screen-vs-exact score error ~2.6e-5
// sigma incl. the reference's own fl(sumxx+cnorm) quantization; MARGIN=3e-4.
//
// Perf intent vs R8 (fp32 FFMA2, 107us): HFMA2 keeps 2 MAC/instr on the fma
// pipe but halves codebook LDS bytes & instr count (L1 62% -> ~32%) and
// halves x register footprint, cutting the LDS-latency stalls that held
// issue at 45%.
//
// (R14 bench aborted with a container-side "system not yet initialized"
// driver error before any kernel ran — resubmitting unchanged.)

#define CD      64
#define HW      4096
#define NC      512
#define THREADS 256
#define MARGIN  3e-4f

typedef uint32_t u32;

// d = a*b + c (packed fp16x2); halves = two consecutive DIMS of one code.
__device__ __forceinline__ u32 hfma2_(u32 a, u32 b, u32 c) {
    u32 d;
    asm("fma.rn.f16x2 %0, %1, %2, %3;" : "=r"(d) : "r"(a), "r"(b), "r"(c));
    return d;
}
__device__ __forceinline__ u32 h2bits(float lo, float hi) {
    __half2 h = __floats2half2_rn(lo, hi);
    return *(u32*)&h;
}
__device__ __forceinline__ float h2sum(u32 v) {      // fp32(lo) + fp32(hi)
    __half2 h = *(__half2*)&v;
    return __low2float(h) + __high2float(h);
}

extern __shared__ char smem[];   // cbH u32[32][512] (64KB) then cnorm f32[512]

__global__ void __launch_bounds__(THREADS, 1) vq_kernel(
    const float* __restrict__ in, const float* __restrict__ cb, float* __restrict__ out)
{
    const int t = threadIdx.x, lid = t & 31;
    u32*   cbH = (u32*)smem;                         // cbH[dp*512 + k] = (c[2dp], c[2dp+1])
    float* cn  = (float*)(smem + 32 * NC * 4);

    // ---- stage codebook fp16 + exact fp32 cnorm (sequential, R6 recipe) ----
    for (int k = t; k < NC; k += THREADS) {
        const float4* src = (const float4*)(cb + (size_t)k * CD);
        float s = 0.f;
        #pragma unroll
        for (int j = 0; j < 16; j++) {
            float4 v = src[j];
            s = __fadd_rn(s, __fmul_rn(v.x, v.x));
            s = __fadd_rn(s, __fmul_rn(v.y, v.y));
            s = __fadd_rn(s, __fmul_rn(v.z, v.z));
            s = __fadd_rn(s, __fmul_rn(v.w, v.w));
            cbH[(2 * j)     * NC + k] = h2bits(v.x, v.y);   // consecutive k per lane
            cbH[(2 * j + 1) * NC + k] = h2bits(v.z, v.w);
        }
        cn[k] = s;
    }
    __syncthreads();

    // ---- load TWO x vectors; exact sumxx; pack fp16 dim-pairs ----
    const int m0 = blockIdx.x * 512;
    const int mA = m0 + t, mB = mA + 256;
    const float* xA = in + (size_t)(mA >> 12) * (CD * HW) + (mA & (HW - 1));
    const float* xB = xA + 256;                      // same image (512 | 4096)

    u32 x2a[32], x2b[32];
    float sxa = 0.f, sxb = 0.f;
    #pragma unroll
    for (int dp = 0; dp < 32; dp++) {
        float a0 = __ldg(xA + (2 * dp) * HW), a1 = __ldg(xA + (2 * dp + 1) * HW);
        float b0 = __ldg(xB + (2 * dp) * HW), b1 = __ldg(xB + (2 * dp + 1) * HW);
        sxa = __fadd_rn(sxa, __fmul_rn(a0, a0)); sxa = __fadd_rn(sxa, __fmul_rn(a1, a1));
        sxb = __fadd_rn(sxb, __fmul_rn(b0, b0)); sxb = __fadd_rn(sxb, __fmul_rn(b1, b1));
        x2a[dp] = h2bits(a0, a1);
        x2b[dp] = h2bits(b0, b1);
    }

    // ---- fp16 screen: 16 codes/tile; per code one HFMA2 chain over 32 dim-pairs ----
    float bA1 = INFINITY, bA2 = INFINITY, bB1 = INFINITY, bB2 = INFINITY;
    int   iA = 0, iB = 0;

    for (int k0 = 0; k0 < NC; k0 += 16) {
        u32 aA[16], aB[16];
        #pragma unroll
        for (int i = 0; i < 16; i++) { aA[i] = 0u; aB[i] = 0u; }

        #pragma unroll
        for (int dp = 0; dp < 32; dp++) {
            const uint4* row = (const uint4*)(cbH + dp * NC + k0);  // broadcast LDS.128
            uint4 c0 = row[0], c1 = row[1], c2 = row[2], c3 = row[3];
            const u32 cc[16] = { c0.x, c0.y, c0.z, c0.w, c1.x, c1.y, c1.z, c1.w,
                                 c2.x, c2.y, c2.z, c2.w, c3.x, c3.y, c3.z, c3.w };
            const u32 xa = x2a[dp], xb = x2b[dp];
            #pragma unroll
            for (int i = 0; i < 16; i++) {
                aA[i] = hfma2_(xa, cc[i], aA[i]);
                aB[i] = hfma2_(xb, cc[i], aB[i]);
            }
        }
        // screen epilogue: s = cnorm - 2*dot16 (fp32); ascending k, strict '<'
        #pragma unroll
        for (int i = 0; i < 16; i++) {
            const int k = k0 + i;
            const float cnk = cn[k];
            float v = fmaf(-2.f, h2sum(aA[i]), cnk);
            if (v < bA1) { bA2 = bA1; bA1 = v; iA = k; } else if (v < bA2) bA2 = v;
            v = fmaf(-2.f, h2sum(aB[i]), cnk);
            if (v < bB1) { bB2 = bB1; bB1 = v; iB = k; } else if (v < bB2) bB2 = v;
        }
    }

    // ---- exact rescreen of flagged rows (bit-exact R6 recipe), warp-coop ----
    auto rescreen = [&](bool flag, int m, int& bi) {
        unsigned msk = __ballot_sync(0xffffffffu, flag);
        while (msk) {
            const int src = __ffs(msk) - 1;
            msk &= msk - 1;
            const int vm = __shfl_sync(0xffffffffu, m, src);
            const float* xv = in + (size_t)(vm >> 12) * (CD * HW) + (vm & (HW - 1));
            float xr[CD];
            #pragma unroll
            for (int d = 0; d < CD; d++) xr[d] = __ldg(xv + d * HW);  // broadcast
            float sx = 0.f;
            #pragma unroll
            for (int d = 0; d < CD; d++) sx = __fadd_rn(sx, __fmul_rn(xr[d], xr[d]));

            float bv = INFINITY; int bk = 0;
            for (int kk = 0; kk < 16; kk++) {          // lane: codes 16*lid.. ascending
                const int k = lid * 16 + kk;
                const float4* cr = (const float4*)(cb + (size_t)k * CD);
                float dot = 0.f;
                #pragma unroll
                for (int j = 0; j < 16; j++) {         // exact: sequential-d FMA
                    float4 c4 = __ldg(cr + j);
                    dot = __fmaf_rn(xr[4 * j + 0], c4.x, dot);
                    dot = __fmaf_rn(xr[4 * j + 1], c4.y, dot);
                    dot = __fmaf_rn(xr[4 * j + 2], c4.z, dot);
                    dot = __fmaf_rn(xr[4 * j + 3], c4.w, dot);
                }
                const float v = __fsub_rn(__fadd_rn(sx, cn[k]), __fmul_rn(2.f, dot));
                if (v < bv) { bv = v; bk = k; }
            }
            #pragma unroll
            for (int o = 16; o; o >>= 1) {             // lexicographic (v,k) min
                const float ov = __shfl_down_sync(0xffffffffu, bv, o);
                const int   ok = __shfl_down_sync(0xffffffffu, bk, o);
                if (ov < bv || (ov == bv && ok < bk)) { bv = ov; bk = ok; }
            }
            const int win = __shfl_sync(0xffffffffu, bk, 0);
            if (lid == src) bi = win;
        }
    };
    rescreen((bA2 - bA1) < MARGIN, mA, iA);
    rescreen((bB2 - bB1) < MARGIN, mB, iB);

    // ---- write winning codebook rows (L2-hot gather) ----
    {
        const float4* srcA = (const float4*)(cb + (size_t)iA * CD);
        const float4* srcB = (const float4*)(cb + (size_t)iB * CD);
        float4* dstA = (float4*)(out + (size_t)mA * CD);
        float4* dstB = (float4*)(out + (size_t)mB * CD);
        #pragma unroll
        for (int j = 0; j < 16; j++) dstA[j] = __ldg(srcA + j);
        #pragma unroll
        for (int j = 0; j < 16; j++) dstB[j] = __ldg(srcB + j);
    }
}

extern "C" void kernel_launch(void* const* d_in, const int* in_sizes, int n_in,
                              void* d_out, int out_size)
{
    const float* in = (const float*)d_in[0];   // (16,64,64,64) fp32
    const float* cb = (const float*)d_in[1];   // (512,64) fp32
    float* out = (float*)d_out;

    const int smem_bytes = 32 * NC * 4 + NC * 4;    // 64KB + 2KB
    cudaFuncSetAttribute(vq_kernel, cudaFuncAttributeMaxDynamicSharedMemorySize, smem_bytes);
    vq_kernel<<<65536 / 512, THREADS, smem_bytes>>>(in, cb, out);
}